// round 2
// baseline (speedup 1.0000x reference)
#include <cuda_runtime.h>
#include <math.h>

#define NV 2
#define NB 16384
#define NC 100
#define ND 512
#define ROWS_PER_BLOCK 8
#define BLOCKS_PER_V (NB / ROWS_PER_BLOCK)      // 2048
#define MAIN_BLOCKS (NV * BLOCKS_PER_V)         // 4096
#define MARGIN_F 10.0f

// Scratch (no dynamic allocation allowed)
__device__ float g_partials[MAIN_BLOCKS];   // per-block diff^2 partial sums
__device__ float g_inter[NV];               // per-v inter_loss

__global__ void __launch_bounds__(256) anchor_loss_main(
    const float* __restrict__ feat,
    const int* __restrict__ label,           // int32 (JAX x64 disabled)
    const float* __restrict__ anchor,
    float* __restrict__ out)                 // out[0]=loss, out[1..]=sims
{
    if (blockIdx.x < MAIN_BLOCKS) {
        // ---- main pass: one warp per (v, b) row ----
        const int warp = threadIdx.x >> 5;
        const int lane = threadIdx.x & 31;
        const int row  = blockIdx.x * ROWS_PER_BLOCK + warp;   // 0..32767
        const int v    = row >> 14;                            // /NB
        const int b    = row & (NB - 1);

        const float4* f4 = reinterpret_cast<const float4*>(feat)
                           + (size_t)row * (ND / 4);
        int lbl = label[b];
        lbl = min(max(lbl, 0), NC - 1);                        // safety clamp
        const float4* c4 = reinterpret_cast<const float4*>(anchor)
                           + ((size_t)v * NC + lbl) * (ND / 4);

        float ds = 0.f, dt = 0.f, fn = 0.f, cn = 0.f;
        #pragma unroll
        for (int k = 0; k < 4; k++) {
            float4 f = f4[lane + 32 * k];
            float4 c = c4[lane + 32 * k];
            float d0 = f.x - c.x, d1 = f.y - c.y, d2 = f.z - c.z, d3 = f.w - c.w;
            ds = fmaf(d0, d0, fmaf(d1, d1, fmaf(d2, d2, fmaf(d3, d3, ds))));
            dt = fmaf(f.x, c.x, fmaf(f.y, c.y, fmaf(f.z, c.z, fmaf(f.w, c.w, dt))));
            fn = fmaf(f.x, f.x, fmaf(f.y, f.y, fmaf(f.z, f.z, fmaf(f.w, f.w, fn))));
            cn = fmaf(c.x, c.x, fmaf(c.y, c.y, fmaf(c.z, c.z, fmaf(c.w, c.w, cn))));
        }
        #pragma unroll
        for (int off = 16; off > 0; off >>= 1) {
            ds += __shfl_xor_sync(0xffffffffu, ds, off);
            dt += __shfl_xor_sync(0xffffffffu, dt, off);
            fn += __shfl_xor_sync(0xffffffffu, fn, off);
            cn += __shfl_xor_sync(0xffffffffu, cn, off);
        }

        __shared__ float sh[ROWS_PER_BLOCK];
        if (lane == 0) {
            float denom = fmaxf(sqrtf(fn), 1e-8f) * fmaxf(sqrtf(cn), 1e-8f);
            out[1 + row] = dt / denom;
            sh[warp] = ds;
        }
        __syncthreads();
        if (threadIdx.x == 0) {
            float t = 0.f;
            #pragma unroll
            for (int w = 0; w < ROWS_PER_BLOCK; w++) t += sh[w];
            g_partials[blockIdx.x] = t;
        }
    } else {
        // ---- anchor stats: one block per v ----
        // pair_sum = C * sum_c ||a_c||^2 - ||sum_c a_c||^2 (pd diagonal is 0)
        const int v = blockIdx.x - MAIN_BLOCKS;
        const int t = threadIdx.x;          // 0..255, covers d and d+256
        const float* a = anchor + (size_t)v * NC * ND;

        float m0 = 0.f, m1 = 0.f, s = 0.f;
        #pragma unroll 4
        for (int c = 0; c < NC; c++) {
            float x0 = a[(size_t)c * ND + t];
            float x1 = a[(size_t)c * ND + t + 256];
            m0 += x0; m1 += x1;
            s = fmaf(x0, x0, fmaf(x1, x1, s));
        }
        float q = fmaf(m0, m0, m1 * m1);

        __shared__ float shs[256], shq[256];
        shs[t] = s; shq[t] = q;
        __syncthreads();
        #pragma unroll
        for (int off = 128; off > 0; off >>= 1) {
            if (t < off) { shs[t] += shs[t + off]; shq[t] += shq[t + off]; }
            __syncthreads();
        }
        if (t == 0) {
            float S = shs[0];          // sum_c ||a_c||^2
            float M2 = shq[0];         // ||sum_c a_c||^2
            float inter = (NC * S - M2) / (float)(NC * (NC - 1));
            g_inter[v] = fmaxf(MARGIN_F - inter, 0.0f);
        }
    }
}

__global__ void __launch_bounds__(256) anchor_loss_finalize(float* __restrict__ out)
{
    const int t = threadIdx.x;  // 256 threads
    float t0 = 0.f, t1 = 0.f;
    #pragma unroll
    for (int k = 0; k < 8; k++) {
        t0 += g_partials[t + 256 * k];                       // v = 0 partials
        t1 += g_partials[BLOCKS_PER_V + t + 256 * k];        // v = 1 partials
    }
    __shared__ float s0[256], s1[256];
    s0[t] = t0; s1[t] = t1;
    __syncthreads();
    #pragma unroll
    for (int off = 128; off > 0; off >>= 1) {
        if (t < off) { s0[t] += s0[t + off]; s1[t] += s1[t + off]; }
        __syncthreads();
    }
    if (t == 0) {
        // mean over v of (sum/(2B)):
        float center_mean = (s0[0] + s1[0]) / (2.0f * (float)NV * (float)NB);
        float inter_mean  = (g_inter[0] + g_inter[1]) / (float)NV;
        out[0] = center_mean + inter_mean;
    }
}

extern "C" void kernel_launch(void* const* d_in, const int* in_sizes, int n_in,
                              void* d_out, int out_size)
{
    const float* feat   = (const float*)d_in[0];
    const int*   label  = (const int*)d_in[1];
    const float* anchor = (const float*)d_in[2];
    float* out = (float*)d_out;

    anchor_loss_main<<<MAIN_BLOCKS + NV, 256>>>(feat, label, anchor, out);
    anchor_loss_finalize<<<1, 256>>>(out);
}